// round 14
// baseline (speedup 1.0000x reference)
#include <cuda_runtime.h>

#define NCLS  80
#define HGT   76
#define WID   76
#define HW    (HGT * WID)          // 5776 (even)
#define NCELL (16 * 3 * HW)        // 277248
#define NPAIR (NCELL / 2)          // 138624
#define CH    (5 + NCLS)           // 85

#define NTHREADS 256
#define NBLOCKS  ((NPAIR + NTHREADS - 1) / NTHREADS)   // 542
#define NWARPS   (NTHREADS / 32)                       // 8

// accumulator slots
enum { SX = 0, SY, SW, SH, SCM, SCN, SCLS, CNT, NCNT, NACC };

__device__ float g_part[NBLOCKS][16];   // row padded to 64B

// softplus(z) = log(1+e^z) = -log(1-sigmoid(z)); softplus(-z) = -log(sigmoid(z))
__device__ __forceinline__ float splus(float z) {
    z = fminf(fmaxf(z, -16.0f), 16.0f);
    return __logf(1.0f + __expf(z));
}
// bce(sigmoid(z), t) = softplus(z) - t*z (exact identity)
__device__ __forceinline__ float bce_z(float z, float t) {
    z = fminf(fmaxf(z, -16.0f), 16.0f);
    return __logf(1.0f + __expf(z)) - t * z;
}
__device__ __forceinline__ float warp_sum(float v) {
    #pragma unroll
    for (int off = 16; off > 0; off >>= 1)
        v += __shfl_down_sync(0xFFFFFFFFu, v, off);
    return v;
}
__device__ __forceinline__ double warp_sum_d(double v) {
    #pragma unroll
    for (int off = 16; off > 0; off >>= 1)
        v += __shfl_down_sync(0xFFFFFFFFu, v, off);
    return v;
}

// ---------------------------------------------------------------------------
// MAIN: unchanged R9/R13 body (542x256, 2 cells/thread, softplus identity,
// mask dtype autodetect, warp-coop sparse path). Writes per-block partials.
// ---------------------------------------------------------------------------
__global__ void __launch_bounds__(NTHREADS)
k_main(const float* __restrict__ inp,
       const void*  __restrict__ mask_p,
       const void*  __restrict__ nmask_p,
       const float* __restrict__ tx,
       const float* __restrict__ ty,
       const float* __restrict__ tw,
       const float* __restrict__ th,
       const float* __restrict__ tcls,
       const float* __restrict__ bls) {
    __shared__ float sh[NWARPS][NACC];

    const int lane = threadIdx.x & 31;
    const int wrp  = threadIdx.x >> 5;
    const int p    = blockIdx.x * NTHREADS + threadIdx.x;  // pair index
    const bool act = (p < NPAIR);

    // --- per-warp mask dtype detect (one broadcast load + warp OR) ---
    const unsigned wv =
        __reduce_or_sync(0xFFFFFFFFu, ((const unsigned*)nmask_p)[lane]);
    int mode;
    if (wv & 0x3E000000u)      mode = 1;  // float32
    else if (wv & 0xFFFFFF00u) mode = 0;  // uint8
    else                       mode = 2;  // int32

    // --- vector mask loads (2 cells) ---
    bool m[2] = {false, false}, nm[2] = {false, false};
    if (act) {
        if (mode == 1) {
            const float2 mf = ((const float2*)mask_p)[p];
            const float2 nf = ((const float2*)nmask_p)[p];
            m[0] = mf.x != 0.0f;  m[1] = mf.y != 0.0f;
            nm[0] = nf.x != 0.0f; nm[1] = nf.y != 0.0f;
        } else if (mode == 2) {
            const int2 mi = ((const int2*)mask_p)[p];
            const int2 ni = ((const int2*)nmask_p)[p];
            m[0] = mi.x != 0;  m[1] = mi.y != 0;
            nm[0] = ni.x != 0; nm[1] = ni.y != 0;
        } else {
            const unsigned short mu = ((const unsigned short*)mask_p)[p];
            const unsigned short nu = ((const unsigned short*)nmask_p)[p];
            m[0] = (mu & 0xFFu) != 0;  m[1] = (mu >> 8) != 0;
            nm[0] = (nu & 0xFFu) != 0; nm[1] = (nu >> 8) != 0;
        }
    }

    // --- dense conf path: raw logits only ---
    const int n0   = p * 2;
    const int hw0  = n0 % HW;
    const int ba   = n0 / HW;              // pairs never cross a plane (HW even)
    const int base = ba * CH * HW + hw0;   // channel-0 offset of cell 0

    float z4[2] = {0.0f, 0.0f};
    if (act) {
        const float2 cz = *(const float2*)(inp + base + 4 * HW);
        z4[0] = cz.x;  z4[1] = cz.y;
    }

    // loss_conf noobj term: -log(1-sigm(z)) = softplus(z)
    float scn = 0.0f;
    #pragma unroll
    for (int j = 0; j < 2; j++)
        if (nm[j]) scn += splus(z4[j]);

    const unsigned nmb0 = __ballot_sync(0xFFFFFFFFu, nm[0]);
    const unsigned nmb1 = __ballot_sync(0xFFFFFFFFu, nm[1]);

    float a[NACC];
    #pragma unroll
    for (int q = 0; q < NACC; q++) a[q] = 0.0f;
    {
        const float wscn = warp_sum(scn);
        if (lane == 0) {
            a[SCN]  = wscn;
            a[NCNT] = (float)(__popc(nmb0) + __popc(nmb1));
        }
    }

    // --- sparse path: warp-cooperative per masked cell ---
    const int warp_p0 = blockIdx.x * NTHREADS + wrp * 32;  // first pair of warp
    #pragma unroll
    for (int j = 0; j < 2; j++) {
        unsigned mb = __ballot_sync(0xFFFFFFFFu, m[j]);
        if (lane == 0) a[CNT] += (float)__popc(mb);
        while (mb) {
            const int src = __ffs(mb) - 1;
            mb &= mb - 1;

            const int n_s    = (warp_p0 + src) * 2 + j;
            const int hw_s   = n_s % HW;
            const int ba_s   = n_s / HW;
            const int base_s = ba_s * CH * HW + hw_s;

            // 80-class BCE split across 32 lanes: softplus(z) - t*z
            float sc = 0.0f;
            #pragma unroll
            for (int k = lane; k < NCLS; k += 32) {
                sc += bce_z(inp[base_s + (5 + k) * HW],
                            tcls[(long long)n_s * NCLS + k]);
            }
            sc = warp_sum(sc);                            // total in lane 0

            const float z4_s = __shfl_sync(0xFFFFFFFFu, z4[j], src);

            if (lane == 0) {
                const float s   = bls[n_s];
                const float zx  = inp[base_s];
                const float zy  = inp[base_s + HW];
                const float wvv = inp[base_s + 2 * HW];
                const float hvv = inp[base_s + 3 * HW];
                a[SX] += bce_z(zx, tx[n_s]) * s;
                a[SY] += bce_z(zy, ty[n_s]) * s;
                const float dw = wvv - tw[n_s];
                const float dh = hvv - th[n_s];
                a[SW]   += dw * dw * s;
                a[SH]   += dh * dh * s;
                a[SCM]  += splus(-z4_s);    // -log(sigm(z))
                a[SCLS] += sc;
            }
        }
    }

    // --- block combine: plain global store, no fence/atomic ---
    if (lane == 0) {
        #pragma unroll
        for (int q = 0; q < NACC; q++) sh[wrp][q] = a[q];
    }
    __syncthreads();

    if (threadIdx.x == 0) {
        #pragma unroll
        for (int q = 0; q < NACC; q++) {
            float r = 0.0f;
            #pragma unroll
            for (int w = 0; w < NWARPS; w++) r += sh[w][q];
            g_part[blockIdx.x][q] = r;
        }
    }
}

// ---------------------------------------------------------------------------
// FINALIZE v2: MLP-maximized. Thread layout:
//   j = tid >> 6  (slot group: float4 covering slots 4j..4j+3; j=0..3)
//   r = tid & 63  (starting row; rows strided by 64)
// Each thread: ceil(542/64)=9 INDEPENDENT float4 loads -> double4 acc.
// Then: double4 warp-sum (warps 2j, 2j+1) -> smem -> thread 0 finalizes.
// ---------------------------------------------------------------------------
__global__ void __launch_bounds__(NTHREADS)
k_final(float* __restrict__ out, int out_size) {
    __shared__ double s_w[NWARPS][4];

    const int tid  = threadIdx.x;
    const int lane = tid & 31;
    const int wrp  = tid >> 5;
    const int j    = tid >> 6;   // slot group 0..3
    const int r    = tid & 63;   // starting row

    double ax = 0.0, ay = 0.0, az = 0.0, aw = 0.0;
    #pragma unroll
    for (int it = 0; it < (NBLOCKS + 63) / 64; it++) {
        const int b = r + it * 64;
        if (b < NBLOCKS) {
            const float4 v = *(const float4*)&g_part[b][4 * j];
            ax += v.x; ay += v.y; az += v.z; aw += v.w;
        }
    }
    ax = warp_sum_d(ax); ay = warp_sum_d(ay);
    az = warp_sum_d(az); aw = warp_sum_d(aw);
    if (lane == 0) {
        s_w[wrp][0] = ax; s_w[wrp][1] = ay; s_w[wrp][2] = az; s_w[wrp][3] = aw;
    }
    __syncthreads();

    if (tid == 0) {
        double t[16];
        #pragma unroll
        for (int g = 0; g < 4; g++)
            #pragma unroll
            for (int k = 0; k < 4; k++)
                t[4 * g + k] = s_w[2 * g][k] + s_w[2 * g + 1][k];

        const double cnt  = t[CNT];
        const double ncnt = t[NCNT];
        const double loss =
            2.5 * (t[SX] + t[SY] + t[SW] + t[SH]) / cnt
            + t[SCM] / cnt
            + t[SCN] / ncnt
            + t[SCLS] / (cnt * (double)NCLS);
        const float lf = (float)loss;
        for (int i = 0; i < out_size; i++) out[i] = lf;
    }
}

extern "C" void kernel_launch(void* const* d_in, const int* in_sizes, int n_in,
                              void* d_out, int out_size) {
    const float* inp   = (const float*)d_in[0];
    const void*  mask  = d_in[1];
    const void*  nmask = d_in[2];
    const float* tx    = (const float*)d_in[3];
    const float* ty    = (const float*)d_in[4];
    const float* tw    = (const float*)d_in[5];
    const float* th    = (const float*)d_in[6];
    // d_in[7] = tconf: redundant (tconf==1 <=> mask==1, noobj=0 there)
    const float* tcls  = (const float*)d_in[8];
    const float* bls   = (const float*)d_in[9];

    k_main<<<NBLOCKS, NTHREADS>>>(inp, mask, nmask, tx, ty, tw, th, tcls, bls);
    k_final<<<1, NTHREADS>>>((float*)d_out, out_size);
}

// round 15
// speedup vs baseline: 1.0152x; 1.0152x over previous
#include <cuda_runtime.h>

#define NCLS  80
#define HGT   76
#define WID   76
#define HW    (HGT * WID)          // 5776 (even)
#define NCELL (16 * 3 * HW)        // 277248
#define NPAIR (NCELL / 2)          // 138624
#define CH    (5 + NCLS)           // 85

#define NTHREADS 256
#define NBLOCKS  ((NPAIR + NTHREADS - 1) / NTHREADS)   // 542
#define NWARPS   (NTHREADS / 32)                       // 8
#define FBLOCKS  148                                   // full wave: defeats low-grid issue throttle

// accumulator slots
enum { SX = 0, SY, SW, SH, SCM, SCN, SCLS, CNT, NCNT, NACC };

__device__ float g_part[NBLOCKS][16];   // row padded to 64B

// softplus(z) = log(1+e^z) = -log(1-sigmoid(z)); softplus(-z) = -log(sigmoid(z))
__device__ __forceinline__ float splus(float z) {
    z = fminf(fmaxf(z, -16.0f), 16.0f);
    return __logf(1.0f + __expf(z));
}
// bce(sigmoid(z), t) = softplus(z) - t*z (exact identity)
__device__ __forceinline__ float bce_z(float z, float t) {
    z = fminf(fmaxf(z, -16.0f), 16.0f);
    return __logf(1.0f + __expf(z)) - t * z;
}
__device__ __forceinline__ float warp_sum(float v) {
    #pragma unroll
    for (int off = 16; off > 0; off >>= 1)
        v += __shfl_down_sync(0xFFFFFFFFu, v, off);
    return v;
}
__device__ __forceinline__ double warp_sum_d(double v) {
    #pragma unroll
    for (int off = 16; off > 0; off >>= 1)
        v += __shfl_down_sync(0xFFFFFFFFu, v, off);
    return v;
}

// ---------------------------------------------------------------------------
// MAIN: unchanged best body (542x256, 2 cells/thread, softplus identity,
// mask dtype autodetect, warp-coop sparse path). Writes per-block partials.
// ---------------------------------------------------------------------------
__global__ void __launch_bounds__(NTHREADS)
k_main(const float* __restrict__ inp,
       const void*  __restrict__ mask_p,
       const void*  __restrict__ nmask_p,
       const float* __restrict__ tx,
       const float* __restrict__ ty,
       const float* __restrict__ tw,
       const float* __restrict__ th,
       const float* __restrict__ tcls,
       const float* __restrict__ bls) {
    __shared__ float sh[NWARPS][NACC];

    const int lane = threadIdx.x & 31;
    const int wrp  = threadIdx.x >> 5;
    const int p    = blockIdx.x * NTHREADS + threadIdx.x;  // pair index
    const bool act = (p < NPAIR);

    // --- per-warp mask dtype detect (one broadcast load + warp OR) ---
    const unsigned wv =
        __reduce_or_sync(0xFFFFFFFFu, ((const unsigned*)nmask_p)[lane]);
    int mode;
    if (wv & 0x3E000000u)      mode = 1;  // float32
    else if (wv & 0xFFFFFF00u) mode = 0;  // uint8
    else                       mode = 2;  // int32

    // --- vector mask loads (2 cells) ---
    bool m[2] = {false, false}, nm[2] = {false, false};
    if (act) {
        if (mode == 1) {
            const float2 mf = ((const float2*)mask_p)[p];
            const float2 nf = ((const float2*)nmask_p)[p];
            m[0] = mf.x != 0.0f;  m[1] = mf.y != 0.0f;
            nm[0] = nf.x != 0.0f; nm[1] = nf.y != 0.0f;
        } else if (mode == 2) {
            const int2 mi = ((const int2*)mask_p)[p];
            const int2 ni = ((const int2*)nmask_p)[p];
            m[0] = mi.x != 0;  m[1] = mi.y != 0;
            nm[0] = ni.x != 0; nm[1] = ni.y != 0;
        } else {
            const unsigned short mu = ((const unsigned short*)mask_p)[p];
            const unsigned short nu = ((const unsigned short*)nmask_p)[p];
            m[0] = (mu & 0xFFu) != 0;  m[1] = (mu >> 8) != 0;
            nm[0] = (nu & 0xFFu) != 0; nm[1] = (nu >> 8) != 0;
        }
    }

    // --- dense conf path: raw logits only ---
    const int n0   = p * 2;
    const int hw0  = n0 % HW;
    const int ba   = n0 / HW;              // pairs never cross a plane (HW even)
    const int base = ba * CH * HW + hw0;   // channel-0 offset of cell 0

    float z4[2] = {0.0f, 0.0f};
    if (act) {
        const float2 cz = *(const float2*)(inp + base + 4 * HW);
        z4[0] = cz.x;  z4[1] = cz.y;
    }

    // loss_conf noobj term: -log(1-sigm(z)) = softplus(z)
    float scn = 0.0f;
    #pragma unroll
    for (int j = 0; j < 2; j++)
        if (nm[j]) scn += splus(z4[j]);

    const unsigned nmb0 = __ballot_sync(0xFFFFFFFFu, nm[0]);
    const unsigned nmb1 = __ballot_sync(0xFFFFFFFFu, nm[1]);

    float a[NACC];
    #pragma unroll
    for (int q = 0; q < NACC; q++) a[q] = 0.0f;
    {
        const float wscn = warp_sum(scn);
        if (lane == 0) {
            a[SCN]  = wscn;
            a[NCNT] = (float)(__popc(nmb0) + __popc(nmb1));
        }
    }

    // --- sparse path: warp-cooperative per masked cell ---
    const int warp_p0 = blockIdx.x * NTHREADS + wrp * 32;  // first pair of warp
    #pragma unroll
    for (int j = 0; j < 2; j++) {
        unsigned mb = __ballot_sync(0xFFFFFFFFu, m[j]);
        if (lane == 0) a[CNT] += (float)__popc(mb);
        while (mb) {
            const int src = __ffs(mb) - 1;
            mb &= mb - 1;

            const int n_s    = (warp_p0 + src) * 2 + j;
            const int hw_s   = n_s % HW;
            const int ba_s   = n_s / HW;
            const int base_s = ba_s * CH * HW + hw_s;

            // 80-class BCE split across 32 lanes: softplus(z) - t*z
            float sc = 0.0f;
            #pragma unroll
            for (int k = lane; k < NCLS; k += 32) {
                sc += bce_z(inp[base_s + (5 + k) * HW],
                            tcls[(long long)n_s * NCLS + k]);
            }
            sc = warp_sum(sc);                            // total in lane 0

            const float z4_s = __shfl_sync(0xFFFFFFFFu, z4[j], src);

            if (lane == 0) {
                const float s   = bls[n_s];
                const float zx  = inp[base_s];
                const float zy  = inp[base_s + HW];
                const float wvv = inp[base_s + 2 * HW];
                const float hvv = inp[base_s + 3 * HW];
                a[SX] += bce_z(zx, tx[n_s]) * s;
                a[SY] += bce_z(zy, ty[n_s]) * s;
                const float dw = wvv - tw[n_s];
                const float dh = hvv - th[n_s];
                a[SW]   += dw * dw * s;
                a[SH]   += dh * dh * s;
                a[SCM]  += splus(-z4_s);    // -log(sigm(z))
                a[SCLS] += sc;
            }
        }
    }

    // --- block combine: plain global store, no fence/atomic ---
    if (lane == 0) {
        #pragma unroll
        for (int q = 0; q < NACC; q++) sh[wrp][q] = a[q];
    }
    __syncthreads();

    if (threadIdx.x == 0) {
        #pragma unroll
        for (int q = 0; q < NACC; q++) {
            float r = 0.0f;
            #pragma unroll
            for (int w = 0; w < NWARPS; w++) r += sh[w][q];
            g_part[blockIdx.x][q] = r;
        }
    }
}

// ---------------------------------------------------------------------------
// FINALIZE v3: grid = 148 (one full wave) to defeat the low-grid issue
// throttle that made grid=1 finalize kernels cost ~10us. Every block
// redundantly computes the same reduce (loads are L2-broadcast, parallel);
// only block 0 writes the result. Thread-parallel output write.
// ---------------------------------------------------------------------------
__global__ void __launch_bounds__(NTHREADS)
k_final(float* __restrict__ out, int out_size) {
    __shared__ double s_w[NWARPS][4];
    __shared__ float  s_lf;

    const int tid  = threadIdx.x;
    const int lane = tid & 31;
    const int wrp  = tid >> 5;
    const int j    = tid >> 6;   // slot group 0..3 (float4 over slots 4j..4j+3)
    const int r    = tid & 63;   // starting row

    double ax = 0.0, ay = 0.0, az = 0.0, aw = 0.0;
    #pragma unroll
    for (int it = 0; it < (NBLOCKS + 63) / 64; it++) {
        const int b = r + it * 64;
        if (b < NBLOCKS) {
            const float4 v = *(const float4*)&g_part[b][4 * j];
            ax += v.x; ay += v.y; az += v.z; aw += v.w;
        }
    }
    ax = warp_sum_d(ax); ay = warp_sum_d(ay);
    az = warp_sum_d(az); aw = warp_sum_d(aw);
    if (lane == 0) {
        s_w[wrp][0] = ax; s_w[wrp][1] = ay; s_w[wrp][2] = az; s_w[wrp][3] = aw;
    }
    __syncthreads();

    if (tid == 0) {
        double t[16];
        #pragma unroll
        for (int g = 0; g < 4; g++)
            #pragma unroll
            for (int k = 0; k < 4; k++)
                t[4 * g + k] = s_w[2 * g][k] + s_w[2 * g + 1][k];

        const double cnt  = t[CNT];
        const double ncnt = t[NCNT];
        const double loss =
            2.5 * (t[SX] + t[SY] + t[SW] + t[SH]) / cnt
            + t[SCM] / cnt
            + t[SCN] / ncnt
            + t[SCLS] / (cnt * (double)NCLS);
        s_lf = (float)loss;
    }
    __syncthreads();

    if (blockIdx.x == 0) {
        const float lf = s_lf;
        for (int i = tid; i < out_size; i += NTHREADS) out[i] = lf;
    }
}

extern "C" void kernel_launch(void* const* d_in, const int* in_sizes, int n_in,
                              void* d_out, int out_size) {
    const float* inp   = (const float*)d_in[0];
    const void*  mask  = d_in[1];
    const void*  nmask = d_in[2];
    const float* tx    = (const float*)d_in[3];
    const float* ty    = (const float*)d_in[4];
    const float* tw    = (const float*)d_in[5];
    const float* th    = (const float*)d_in[6];
    // d_in[7] = tconf: redundant (tconf==1 <=> mask==1, noobj=0 there)
    const float* tcls  = (const float*)d_in[8];
    const float* bls   = (const float*)d_in[9];

    k_main<<<NBLOCKS, NTHREADS>>>(inp, mask, nmask, tx, ty, tw, th, tcls, bls);
    k_final<<<FBLOCKS, NTHREADS>>>((float*)d_out, out_size);
}